// round 10
// baseline (speedup 1.0000x reference)
#include <cuda_runtime.h>

// CTC batch cost, linear-domain forward. v4: gather-interleaved steps.
// vs v3: next-period LDS prob gather is folded into the step loop (overlapped
// with compute) instead of a serial block at the period boundary.
// One warp per batch item; lane l owns states 4l..4l+3.

#define Bc 256
#define Tc 512
#define Cc 128
#define Uc 48
#define BLANKC 127
#define FULLM 0xffffffffu
#define EBIAS 207          // 127 + 80: renorm target exponent 2^80

__device__ __forceinline__ float lg2f_(float x) {
    float y; asm("lg2.approx.f32 %0, %1;" : "=f"(y) : "f"(x)); return y;
}
__device__ __forceinline__ unsigned smem_u32(const void* p) {
    unsigned a;
    asm("{ .reg .u64 t; cvta.to.shared.u64 t, %1; cvt.u32.u64 %0, t; }"
        : "=r"(a) : "l"(p));
    return a;
}
__device__ __forceinline__ void cpa16(unsigned dst, const void* src) {
    asm volatile("cp.async.cg.shared.global [%0], [%1], 16;"
                 :: "r"(dst), "l"(src) : "memory");
}
__device__ __forceinline__ void cpcommit() {
    asm volatile("cp.async.commit_group;" ::: "memory");
}
__device__ __forceinline__ void cpwait2() {
    asm volatile("cp.async.wait_group 2;" ::: "memory");
}
__device__ __forceinline__ void cpwait3() {
    asm volatile("cp.async.wait_group 3;" ::: "memory");
}
__device__ __forceinline__ int iclamp(int v, int lo, int hi) {
    return v < lo ? lo : (v > hi ? hi : v);
}
__device__ __forceinline__ float p2f(int e) {      // exact 2^e, e in [-126,126]
    return __int_as_float((unsigned)(127 + e) << 23);
}

// One timestep. Consumes pa3 (prev step's shfl), issues next shfl early.
#define STEP(J, SCL_, SK1S_) do {                                            \
    float a01 = a0 + a1;                                                     \
    float a23 = a2 + a3;                                                     \
    float a12 = a1 + a2;                                                     \
    float n3 = fmaf(sk3, a1, a23) * P1[J];                                   \
    float pa3n = __shfl_up_sync(FULLM, n3, 1);                               \
    float n2 = a12 * Pb[J];                                                  \
    float n1 = fmaf((SK1S_), pa3, a01) * P0[J];                              \
    float n0 = fmaf((SCL_), pa3, a0) * Pb[J];                                \
    a0 = n0; a1 = n1; a2 = n2; a3 = n3; pa3 = pa3n;                          \
} while (0)

__global__ __launch_bounds__(64)
void ctc_lin4_kernel(const void* __restrict__ yt_raw,
                     const float* __restrict__ y_pred,
                     float* __restrict__ out)
{
    __shared__ __align__(128) float rows[2][4][8][Cc];  // [warp][buf][slot][class]

    const int lane = threadIdx.x & 31;
    const int w    = threadIdx.x >> 5;
    const int b    = blockIdx.x * 2 + w;

    // ---- label dtype probe (int64 vs int32), deterministic ----
    const long long* q64 = (const long long*)yt_raw;
    long long v0 = q64[lane * 2], v1 = q64[lane * 2 + 1];
    bool inr = (v0 >= 0 && v0 <= 127 && v1 >= 0 && v1 <= 127);
    bool is64 = __all_sync(FULLM, inr);
    const int* q32 = (const int*)yt_raw;

    // ---- per-lane labels + skip flags ----
    int u0 = 2 * lane, u1 = 2 * lane + 1;
    int cu0 = (u0 < Uc) ? u0 : 0;
    int cu1 = (u1 < Uc) ? u1 : 0;
    int l0 = is64 ? (int)q64[b * Uc + cu0] : q32[b * Uc + cu0];
    int l1 = is64 ? (int)q64[b * Uc + cu1] : q32[b * Uc + cu1];
    int lprev = __shfl_up_sync(FULLM, l1, 1);
    float sk1 = (u0 == 0 || l0 != lprev) ? 1.f : 0.f;
    float sk3 = (l1 != l0) ? 1.f : 0.f;

    const float* base = y_pred + (size_t)b * Tc * Cc;
    const unsigned sbw = smem_u32(&rows[w][0][0][0]);

    // ---- t = 0 init ----
    float a0 = (lane == 0) ? base[BLANKC] : 0.f;
    float a1 = (lane == 0) ? base[l0] : 0.f;
    float a2 = 0.f, a3 = 0.f, pa3 = 0.f;
    int   eacc = 0;
    float scL  = (lane == 0) ? 0.f : 1.f;
    float scL0 = scL;
    float sk1s = sk1 * scL, sk1s0 = sk1s;

    // ---- prefill buffers for periods 0..3 (rows t = 1..32) ----
    for (int p = 0; p < 4; p++) {
        for (int j = 0; j < 8; j++) {
            int t = 1 + 8 * p + j;
            cpa16(sbw + (unsigned)(((p * 8 + j) * Cc) * 4 + lane * 16),
                  base + (size_t)t * Cc + lane * 4);
        }
        cpcommit();
    }
    cpwait3();          // period 0 resident
    __syncwarp();

    // ---- pre-gather period 0 probs into registers ----
    float Pb[8], P0[8], P1[8];
    {
        const float* r = &rows[w][0][0][0];
#pragma unroll
        for (int j = 0; j < 8; j++) {
            Pb[j] = r[j * Cc + BLANKC];
            P0[j] = r[j * Cc + l0];
            P1[j] = r[j * Cc + l1];
        }
    }

    // pending renorm state (computed @ j==5, applied after j==7)
    float sc_p = 1.f, scLn = scL, scL0n = scL;
    int   eacc_p = 0;

    // ---- main loop: periods k = 0..62 (t = 1..504) ----
    for (int k = 0; k < 63; k++) {
        cpwait2();      // buffers for periods k and k+1 resident
        __syncwarp();
        const bool pref = (k + 4 <= 63);
        const unsigned dstb = sbw + (unsigned)((k & 3) * 8 * Cc * 4 + lane * 16);
        const float* rn = &rows[w][(k + 1) & 3][0][0];   // next period's buffer

#pragma unroll
        for (int j = 0; j < 8; j++) {
            if (j == 0) STEP(0, scL0, sk1s0); else STEP(j, scL, sk1s);

            if (pref) {                       // refill this period's buffer
                int t = 8 * (k + 4) + 1 + j;
                if (t > Tc - 1) t = Tc - 1;
                cpa16(dstb + (unsigned)(j * Cc * 4),
                      base + (size_t)t * Cc + lane * 4);
            }

            // gather NEXT period's probs into the slots just consumed;
            // LDS latency overlaps the remaining steps of this period.
            Pb[j] = rn[j * Cc + BLANKC];
            P0[j] = rn[j * Cc + l0];
            P1[j] = rn[j * Cc + l1];

            if (j == 5) {                     // off-chain renorm decision
                float m5 = fmaxf(fmaxf(a0, a1), fmaxf(a2, a3));
                bool alive = (m5 > 0.f);
                int e = ((__float_as_int(m5) >> 23) & 0xff) - EBIAS;
                e = iclamp(e, -126, 126);
                int cand = eacc + e;
                int adopt = __reduce_min_sync(FULLM, alive ? cand : 0x7fffffff);
                int eaccN = alive ? cand : adopt;
                int dsc = alive ? -e : (eacc - adopt);
                sc_p = p2f(iclamp(dsc, -126, 126));
                int eLold = __shfl_up_sync(FULLM, eacc, 1);
                int eLnew = __shfl_up_sync(FULLM, eaccN, 1);
                int de0 = eLold - eaccN;
                int de  = eLnew - eaccN;
                scL0n = (lane == 0 || de0 < -126) ? 0.f : p2f(iclamp(de0, -126, 126));
                scLn  = (lane == 0 || de  < -126) ? 0.f : p2f(iclamp(de,  -126, 126));
                eacc_p = eaccN;
            }
        }
        cpcommit();                            // one group per period (may be empty)

        // ---- apply pending renorm (exact power-of-2, error-free) ----
        a0 *= sc_p; a1 *= sc_p; a2 *= sc_p; a3 *= sc_p;
        eacc = eacc_p;
        scL = scLn; scL0 = scL0n;
        sk1s = sk1 * scL; sk1s0 = sk1 * scL0;
    }

    // ---- epilogue: period 63, t = 505..511 (7 steps; P gathered @ k=62) ----
#pragma unroll
    for (int j = 0; j < 7; j++) {
        if (j == 0) STEP(0, scL0, sk1s0); else STEP(j, scL, sk1s);
    }

    // ---- finish: true = stored * 2^eacc; states 95 (lane23,a3), 96 (lane24,a0)
    float v95 = __shfl_sync(FULLM, a3, 23); int e95 = __shfl_sync(FULLM, eacc, 23);
    float v96 = __shfl_sync(FULLM, a0, 24); int e96 = __shfl_sync(FULLM, eacc, 24);
    if (lane == 0) {
        int em = e95 > e96 ? e95 : e96;
        float s = ldexpf(v95, e95 - em) + ldexpf(v96, e96 - em);
        float ll2 = lg2f_(s) + (float)em;
        out[b] = -ll2 * 0.69314718055994530942f;
    }
}

extern "C" void kernel_launch(void* const* d_in, const int* in_sizes, int n_in,
                              void* d_out, int out_size)
{
    (void)in_sizes; (void)n_in; (void)out_size;
    const void*  y_true = d_in[0];
    const float* y_pred = (const float*)d_in[1];
    float* out = (float*)d_out;
    ctc_lin4_kernel<<<Bc / 2, 64>>>(y_true, y_pred, out);
}